// round 17
// baseline (speedup 1.0000x reference)
#include <cuda_runtime.h>
#include <cstdint>

// Problem constants
#define Bc 4
#define Sc 2048
#define Hc 1024
#define Ec 8
#define Kc 2
#define Tc (Bc * Sc)          // 8192 tokens
#define Pc (Tc * Kc)          // 16384 pairs
#define TILE_M 128
#define MAX_ROWS (Pc + Ec * TILE_M)   // 17408
#define MAX_TILES (MAX_ROWS / TILE_M) // 136

// GEMM tiling: CTA 128x128, BK=32, DOUBLE 32KB smem buffers (64KB dynamic)
#define BM 128
#define BN 128
#define BK 32
#define NITER (Hc / BK)              // 32
#define NTHREADS 256
#define A_FLOATS (BM * BK)           // 4096
#define B_FLOATS (BK * BN)           // 4096
#define STAGE_FLOATS (A_FLOATS + B_FLOATS)   // 8192 floats = 32 KB
#define SMEM_BYTES (2 * STAGE_FLOATS * 4)    // 65536

// ---------------------------------------------------------------------------
// Scratch — EXACTLY the Round-4/13-proven global footprint (142.6 MB total).
// (Beyond it the driver's module arena grows by a 128 MiB granule -> harness
//  violation. Confirmed R13.)
// ---------------------------------------------------------------------------
__device__ int g_is64;
__device__ int g_counts[Ec];
__device__ int g_cursor[Ec];
__device__ int g_expert_off[Ec];
__device__ int g_tile_expert[MAX_TILES];
__device__ int g_slot_token[MAX_ROWS];
__device__ int g_pair_slot[Pc];
__device__ __align__(16) float g_h1[(size_t)MAX_ROWS * Hc];
__device__ __align__(16) float g_y [(size_t)MAX_ROWS * Hc];

// ---------------------------------------------------------------------------
// Helpers (sm_100 baseline; no tcgen05, no cp.async)
// ---------------------------------------------------------------------------
__device__ __forceinline__ float tf32_rn(float x) {
    uint32_t u;
    asm("cvt.rna.tf32.f32 %0, %1;" : "=r"(u) : "f"(x));
    return __uint_as_float(u);
}
__device__ __forceinline__ float4 tf32_rn4(float4 v) {
    v.x = tf32_rn(v.x); v.y = tf32_rn(v.y);
    v.z = tf32_rn(v.z); v.w = tf32_rn(v.w);
    return v;
}

#define MMA_TF32(d, a, b0, b1) \
    asm volatile("mma.sync.aligned.m16n8k8.row.col.f32.tf32.tf32.f32 " \
                 "{%0,%1,%2,%3}, {%4,%5,%6,%7}, {%8,%9}, {%0,%1,%2,%3};" \
                 : "+f"((d)[0]), "+f"((d)[1]), "+f"((d)[2]), "+f"((d)[3]) \
                 : "r"((a)[0]), "r"((a)[1]), "r"((a)[2]), "r"((a)[3]), \
                   "r"(b0), "r"(b1))

// ---------------------------------------------------------------------------
// Routing prologue (validated in Round 4)
// ---------------------------------------------------------------------------
__global__ void detect_kernel(const int* __restrict__ idx) {
    __shared__ int any_nonzero;
    if (threadIdx.x == 0) any_nonzero = 0;
    __syncthreads();
    int found = 0;
    for (int p = threadIdx.x; p < Pc / 2; p += blockDim.x)
        if (idx[2 * p + 1] != 0) found = 1;
    if (found) atomicExch(&any_nonzero, 1);
    __syncthreads();
    if (threadIdx.x == 0) g_is64 = any_nonzero ? 0 : 1;
}
__device__ __forceinline__ int load_expert(const int* idx, int p, int is64) {
    return idx[is64 ? (p << 1) : p] & (Ec - 1);
}
__global__ void init_kernel() {
    int i = blockIdx.x * blockDim.x + threadIdx.x;
    if (i < MAX_ROWS) g_slot_token[i] = -1;
    if (i < Ec) { g_counts[i] = 0; g_cursor[i] = 0; }
}
__global__ void hist_kernel(const int* __restrict__ idx) {
    int p = blockIdx.x * blockDim.x + threadIdx.x;
    if (p < Pc) atomicAdd(&g_counts[load_expert(idx, p, g_is64)], 1);
}
__global__ void scan_kernel() {
    if (threadIdx.x == 0 && blockIdx.x == 0) {
        int off = 0;
        for (int e = 0; e < Ec; e++) {
            g_expert_off[e] = off;
            int nt = (g_counts[e] + TILE_M - 1) / TILE_M;
            for (int i = 0; i < nt; i++) g_tile_expert[off / TILE_M + i] = e;
            off += nt * TILE_M;
        }
        for (int t = off / TILE_M; t < MAX_TILES; t++) g_tile_expert[t] = 0;
    }
}
__global__ void place_kernel(const int* __restrict__ idx) {
    int p = blockIdx.x * blockDim.x + threadIdx.x;
    if (p < Pc) {
        int e = load_expert(idx, p, g_is64);
        int pos = atomicAdd(&g_cursor[e], 1);
        int slot = g_expert_off[e] + pos;
        g_slot_token[slot] = p >> 1;
        g_pair_slot[p] = slot;
    }
}

// ---------------------------------------------------------------------------
// TF32 tensor-core FFN pass. CTA 128x128, BK=32, 256 threads,
// 8 warps (2 m x 4 n), warp tile 64x32 -> acc 64 floats/thread.
// DOUBLE-BUFFERED: one __syncthreads per iter; STS for iter it+1 overlap
// the mma stream of iter it; global prefetch distance 2.
// SMEM swizzle:  A phys = m*32  + (k ^ (4*(m&7)))    [128 x 32]  (proven)
//                B phys = k*128 + (n ^ (8*(k&7)))    [32 x 128]  (proven)
// FIRST: A = gathered hidden rows (raw fp32, rounded here), out = g_h1
// else : A = g_h1 (already rounded),                        out = g_y
// ---------------------------------------------------------------------------
template <bool FIRST>
__global__ __launch_bounds__(NTHREADS)
void ffn_kernel(const float* __restrict__ X,     // hidden (FIRST) / unused
                const float* __restrict__ W,     // raw w1 or w2 (E,H,H)
                const float* __restrict__ bias)
{
    extern __shared__ __align__(16) float smem[];   // 2 * STAGE_FLOATS

    const int tid  = threadIdx.x;
    const int wid  = tid >> 5;
    const int lane = tid & 31;
    const int tile = blockIdx.x;
    const int n0   = blockIdx.y * BN;
    const int e    = g_tile_expert[tile];

    const int wm = (wid & 1) * 64;       // warp m offset (2 warps)
    const int wn = (wid >> 1) * 32;      // warp n offset (4 warps)
    const int r  = lane >> 2;            // 0..7 (groupID)
    const int cc = lane & 3;             // 0..3 (threadID in group)
    const int fourR = 4 * r;

    const float* __restrict__ wexp = W + ((size_t)e << 20);

    // ---- per-thread load/store assignments: A 4x16B, B 4x16B per iter ----
    const float* pA[4]; int oA[4];
    #pragma unroll
    for (int s = 0; s < 4; s++) {
        int idx = s * NTHREADS + tid;          // 0..1023 A 16B-chunks
        int m = idx >> 3, k4 = idx & 7;
        oA[s] = m * 32 + ((k4 * 4) ^ (4 * (m & 7)));
        if (FIRST) {
            int t = g_slot_token[tile * TILE_M + m];
            // padded rows (t<0): read token-0 data; those rows are never consumed
            pA[s] = (t >= 0 ? X + ((size_t)t << 10) : X) + k4 * 4;
        } else {
            pA[s] = g_h1 + (((size_t)(tile * TILE_M + m)) << 10) + k4 * 4;
        }
    }
    const float* pB[4]; int oB[4];
    #pragma unroll
    for (int s = 0; s < 4; s++) {
        int idx = s * NTHREADS + tid;          // 0..1023 B 16B-chunks
        int k = idx >> 5, nn4 = idx & 31;
        oB[s] = A_FLOATS + k * 128 + ((nn4 * 4) ^ (8 * (k & 7)));
        pB[s] = wexp + ((size_t)k << 10) + n0 + nn4 * 4;
    }

    // ---- accumulators: 4 m-frags x 4 n-frags x 4 = 64 regs ----
    float acc[4][4][4];
    #pragma unroll
    for (int mf = 0; mf < 4; mf++)
        #pragma unroll
        for (int f = 0; f < 4; f++)
            #pragma unroll
            for (int q = 0; q < 4; q++) acc[mf][f][q] = 0.f;

    // ---- prologue: iter-0 data -> buf0; prefetch iter-1 into registers ----
    float4 va[4], vb[4];
    #pragma unroll
    for (int s = 0; s < 4; s++) { va[s] = *(const float4*)pA[s]; pA[s] += BK; }
    #pragma unroll
    for (int s = 0; s < 4; s++) { vb[s] = *(const float4*)pB[s]; pB[s] += (size_t)BK << 10; }
    #pragma unroll
    for (int s = 0; s < 4; s++) *(float4*)&smem[oA[s]] = tf32_rn4(va[s]);
    #pragma unroll
    for (int s = 0; s < 4; s++) *(float4*)&smem[oB[s]] = tf32_rn4(vb[s]);
    #pragma unroll
    for (int s = 0; s < 4; s++) { va[s] = *(const float4*)pA[s]; pA[s] += BK; }
    #pragma unroll
    for (int s = 0; s < 4; s++) { vb[s] = *(const float4*)pB[s]; pB[s] += (size_t)BK << 10; }

    #pragma unroll 1
    for (int it = 0; it < NITER; it++) {
        __syncthreads();   // buf[it&1] fully written; prior iter fully done

        // Store iter it+1 into the other buffer (overlaps this iter's MMAs),
        // then prefetch iter it+2 from global.
        if (it + 1 < NITER) {
            float* dst = smem + ((it + 1) & 1) * STAGE_FLOATS;
            #pragma unroll
            for (int s = 0; s < 4; s++) *(float4*)&dst[oA[s]] = tf32_rn4(va[s]);
            #pragma unroll
            for (int s = 0; s < 4; s++) *(float4*)&dst[oB[s]] = tf32_rn4(vb[s]);
            if (it + 2 < NITER) {
                #pragma unroll
                for (int s = 0; s < 4; s++) { va[s] = *(const float4*)pA[s]; pA[s] += BK; }
                #pragma unroll
                for (int s = 0; s < 4; s++) { vb[s] = *(const float4*)pB[s]; pB[s] += (size_t)BK << 10; }
            }
        }

        const uint32_t* sA = (const uint32_t*)(smem + (it & 1) * STAGE_FLOATS);
        const uint32_t* sB = sA + A_FLOATS;

        #pragma unroll
        for (int ks = 0; ks < 4; ks++) {
            const int k0 = ks * 8 + cc;
            const int k1 = k0 + 4;
            const int ka0 = k0 ^ fourR;
            const int ka1 = k1 ^ fourR;

            uint32_t a[4][4];
            #pragma unroll
            for (int mf = 0; mf < 4; mf++) {
                int mA = (wm + mf * 16 + r) * 32;
                a[mf][0] = sA[mA + ka0];
                a[mf][1] = sA[mA + 8 * 32 + ka0];
                a[mf][2] = sA[mA + ka1];
                a[mf][3] = sA[mA + 8 * 32 + ka1];
            }

            const int rowb0 = k0 * 128, xb0 = 8 * cc;        // k0 & 7 == cc
            const int rowb1 = k1 * 128, xb1 = 8 * (cc + 4);  // k1 & 7 == cc+4
            const int nbase = wn + r;
            #pragma unroll
            for (int f = 0; f < 4; f++) {
                uint32_t b0 = sB[rowb0 + ((nbase + f * 8) ^ xb0)];
                uint32_t b1 = sB[rowb1 + ((nbase + f * 8) ^ xb1)];
                #pragma unroll
                for (int mf = 0; mf < 4; mf++)
                    MMA_TF32(acc[mf][f], a[mf], b0, b1);
            }
        }
    }

    // ---- epilogue ----
    const float* bexp = bias + e * Hc + n0 + wn;
    float* obase = FIRST ? g_h1 : g_y;
    const int c2 = cc * 2;
    #pragma unroll
    for (int mf = 0; mf < 4; mf++) {
        size_t row0 = (size_t)(tile * TILE_M + wm + mf * 16 + r);
        float* o0 = obase + (row0 << 10) + n0 + wn;
        float* o1 = o0 + (8 << 10);
        #pragma unroll
        for (int f = 0; f < 4; f++) {
            float2 bb = *(const float2*)(bexp + f * 8 + c2);
            float2 vt, vbo;
            vt.x  = acc[mf][f][0] + bb.x;  vt.y  = acc[mf][f][1] + bb.y;
            vbo.x = acc[mf][f][2] + bb.x;  vbo.y = acc[mf][f][3] + bb.y;
            if (FIRST) {
                vt.x  = tf32_rn(fmaxf(vt.x, 0.f));  vt.y  = tf32_rn(fmaxf(vt.y, 0.f));
                vbo.x = tf32_rn(fmaxf(vbo.x, 0.f)); vbo.y = tf32_rn(fmaxf(vbo.y, 0.f));
            }
            *(float2*)(o0 + f * 8 + c2) = vt;
            *(float2*)(o1 + f * 8 + c2) = vbo;
        }
    }
}

// ---------------------------------------------------------------------------
// Combine: out[t] = w0 * y[slot0] + w1 * y[slot1]
// ---------------------------------------------------------------------------
__global__ void combine_kernel(const float* __restrict__ tkw,
                               float* __restrict__ out)
{
    int gid = blockIdx.x * blockDim.x + threadIdx.x;
    if (gid < Tc * (Hc / 4)) {
        int t = gid >> 8;
        int h4 = gid & 255;
        float w0 = tkw[2 * t];
        float w1 = tkw[2 * t + 1];
        int s0 = g_pair_slot[2 * t];
        int s1 = g_pair_slot[2 * t + 1];
        const float4* y4 = (const float4*)g_y;
        float4 a = y4[(size_t)s0 * (Hc / 4) + h4];
        float4 b = y4[(size_t)s1 * (Hc / 4) + h4];
        float4 rr;
        rr.x = w0 * a.x + w1 * b.x;
        rr.y = w0 * a.y + w1 * b.y;
        rr.z = w0 * a.z + w1 * b.z;
        rr.w = w0 * a.w + w1 * b.w;
        ((float4*)out)[gid] = rr;
    }
}

// ---------------------------------------------------------------------------
extern "C" void kernel_launch(void* const* d_in, const int* in_sizes, int n_in,
                              void* d_out, int out_size)
{
    const float* hidden = (const float*)d_in[0];
    const int*   tk_idx = (const int*)d_in[1];
    const float* tk_w   = (const float*)d_in[2];
    const float* w1     = (const float*)d_in[3];
    const float* b1     = (const float*)d_in[4];
    const float* w2     = (const float*)d_in[5];
    const float* b2     = (const float*)d_in[6];
    float*       out    = (float*)d_out;

    cudaFuncSetAttribute(ffn_kernel<true>,
                         cudaFuncAttributeMaxDynamicSharedMemorySize, SMEM_BYTES);
    cudaFuncSetAttribute(ffn_kernel<false>,
                         cudaFuncAttributeMaxDynamicSharedMemorySize, SMEM_BYTES);

    detect_kernel<<<1, 256>>>(tk_idx);
    init_kernel <<<(MAX_ROWS + 255) / 256, 256>>>();
    hist_kernel <<<(Pc + 255) / 256, 256>>>(tk_idx);
    scan_kernel <<<1, 32>>>();
    place_kernel<<<(Pc + 255) / 256, 256>>>(tk_idx);

    dim3 gg(MAX_TILES, Hc / BN);
    ffn_kernel<true > <<<gg, NTHREADS, SMEM_BYTES>>>(hidden, w1, b1);
    ffn_kernel<false> <<<gg, NTHREADS, SMEM_BYTES>>>(nullptr, w2, b2);

    combine_kernel<<<(Tc * (Hc / 4) + 255) / 256, 256>>>(tk_w, out);
}